// round 1
// baseline (speedup 1.0000x reference)
#include <cuda_runtime.h>
#include <math.h>

#define BATCH 4
#define NPTS  8192
#define TILE  2048          // label points staged in smem per tile (32 KB of float4)
#define BLOCK_THREADS 128
#define PTS_PER_BLOCK 256   // 2 A-points per thread

// Scratch accumulators (allocation-free per harness rules)
__device__ float g_accum[2];

__global__ void chamfer_init_kernel() {
    g_accum[0] = 0.0f;
    g_accum[1] = 0.0f;
}

// blockIdx.z = direction: 0 => pred->label, 1 => label->pred
// blockIdx.y = batch
// blockIdx.x = tile of 256 "A" points
__global__ __launch_bounds__(BLOCK_THREADS)
void chamfer_dir_kernel(const float* __restrict__ pred,
                        const float* __restrict__ label) {
    const int dir = blockIdx.z;
    const float* __restrict__ A  = (dir == 0) ? pred  : label;
    const float* __restrict__ Bv = (dir == 0) ? label : pred;
    const int b = blockIdx.y;
    const float* __restrict__ Abase = A  + (size_t)b * NPTS * 3;
    const float* __restrict__ Bbase = Bv + (size_t)b * NPTS * 3;

    __shared__ float4 sB[TILE];

    const int tid = threadIdx.x;
    const int i0 = blockIdx.x * PTS_PER_BLOCK + tid;
    const int i1 = i0 + BLOCK_THREADS;

    // Load the two A points handled by this thread
    const float ax0 = Abase[i0 * 3 + 0];
    const float ay0 = Abase[i0 * 3 + 1];
    const float az0 = Abase[i0 * 3 + 2];
    const float ax1 = Abase[i1 * 3 + 0];
    const float ay1 = Abase[i1 * 3 + 1];
    const float az1 = Abase[i1 * 3 + 2];
    const float x2_0 = fmaf(ax0, ax0, fmaf(ay0, ay0, az0 * az0));
    const float x2_1 = fmaf(ax1, ax1, fmaf(ay1, ay1, az1 * az1));

    // Track min over j of (||y_j||^2 - 2 x.y_j); add ||x||^2 at the end.
    float m0 = 3.0e38f;
    float m1 = 3.0e38f;

    for (int t0 = 0; t0 < NPTS; t0 += TILE) {
        __syncthreads();
        // Cooperative tile load: TILE points, compute y^2 once here.
        #pragma unroll
        for (int j = tid; j < TILE; j += BLOCK_THREADS) {
            const float* p = Bbase + (size_t)(t0 + j) * 3;
            const float bx = p[0], by = p[1], bz = p[2];
            sB[j] = make_float4(bx, by, bz, fmaf(bx, bx, fmaf(by, by, bz * bz)));
        }
        __syncthreads();

        #pragma unroll 8
        for (int j = 0; j < TILE; j++) {
            const float4 v = sB[j];
            const float d0 = fmaf(v.x, ax0, fmaf(v.y, ay0, v.z * az0));
            const float d1 = fmaf(v.x, ax1, fmaf(v.y, ay1, v.z * az1));
            m0 = fminf(m0, fmaf(-2.0f, d0, v.w));
            m1 = fminf(m1, fmaf(-2.0f, d1, v.w));
        }
    }

    const float dmin0 = sqrtf(fmaxf(x2_0 + m0, 0.0f));
    const float dmin1 = sqrtf(fmaxf(x2_1 + m1, 0.0f));
    float s = dmin0 + dmin1;

    // Warp reduce
    #pragma unroll
    for (int off = 16; off > 0; off >>= 1)
        s += __shfl_down_sync(0xFFFFFFFFu, s, off);

    __shared__ float warp_sums[BLOCK_THREADS / 32];
    if ((tid & 31) == 0) warp_sums[tid >> 5] = s;
    __syncthreads();
    if (tid == 0) {
        float bs = 0.0f;
        #pragma unroll
        for (int w = 0; w < BLOCK_THREADS / 32; w++) bs += warp_sums[w];
        atomicAdd(&g_accum[dir], bs);
    }
}

__global__ void chamfer_finalize_kernel(float* __restrict__ out) {
    const float inv = 1.0f / (float)(BATCH * NPTS);
    out[0] = g_accum[0] * inv + g_accum[1] * inv;
}

extern "C" void kernel_launch(void* const* d_in, const int* in_sizes, int n_in,
                              void* d_out, int out_size) {
    const float* pred  = (const float*)d_in[0];
    const float* label = (const float*)d_in[1];
    float* out = (float*)d_out;

    chamfer_init_kernel<<<1, 1>>>();
    dim3 grid(NPTS / PTS_PER_BLOCK, BATCH, 2);
    chamfer_dir_kernel<<<grid, BLOCK_THREADS>>>(pred, label);
    chamfer_finalize_kernel<<<1, 1>>>(out);
}

// round 2
// speedup vs baseline: 1.5571x; 1.5571x over previous
#include <cuda_runtime.h>
#include <math.h>

#define BATCH 4
#define NPTS  8192
#define NSPLIT 4
#define BRANGE (NPTS / NSPLIT)            // 2048 B-points per block
#define PTS_PER_THREAD 8
#define THREADS 128
#define PTS_PER_BLOCK (PTS_PER_THREAD * THREADS)  // 1024
#define NCHUNK (NPTS / PTS_PER_BLOCK)             // 8

// Partial max(x.y - y^2/2) per (dir, batch, point, split). 1 MB static scratch.
__device__ float g_partial[2 * BATCH * NPTS * NSPLIT];

union U64F2 { unsigned long long u; float2 f; };

__device__ __forceinline__ unsigned long long fma2(unsigned long long a,
                                                   unsigned long long b,
                                                   unsigned long long c) {
    unsigned long long d;
    asm("fma.rn.f32x2 %0, %1, %2, %3;" : "=l"(d) : "l"(a), "l"(b), "l"(c));
    return d;
}

__device__ __forceinline__ unsigned long long pack2(float lo, float hi) {
    U64F2 u; u.f = make_float2(lo, hi); return u.u;
}

__global__ void chamfer_init_kernel(float* __restrict__ out) {
    out[0] = 0.0f;
}

// blockIdx.z = dir*NSPLIT + split ; blockIdx.y = batch ; blockIdx.x = A-chunk
__global__ __launch_bounds__(THREADS)
void chamfer_main_kernel(const float* __restrict__ pred,
                         const float* __restrict__ label) {
    const int z     = blockIdx.z;
    const int dir   = z >> 2;
    const int split = z & 3;
    const int b     = blockIdx.y;
    const float* __restrict__ A  = ((dir == 0) ? pred  : label) + (size_t)b * NPTS * 3;
    const float* __restrict__ Bt = ((dir == 0) ? label : pred)  + (size_t)b * NPTS * 3
                                   + (size_t)split * BRANGE * 3;

    // Pair layout: slot 2q = (bx0,bx1,by0,by1), slot 2q+1 = (bz0,bz1,w0,w1), w = -0.5*||y||^2
    __shared__ float4 sB[BRANGE];   // 32 KB

    const int tid = threadIdx.x;

    // Cooperative tile load + precompute w
    for (int q = tid; q < BRANGE / 2; q += THREADS) {
        const float* p = Bt + (size_t)(2 * q) * 3;
        const float bx0 = p[0], by0 = p[1], bz0 = p[2];
        const float bx1 = p[3], by1 = p[4], bz1 = p[5];
        const float w0 = -0.5f * fmaf(bx0, bx0, fmaf(by0, by0, bz0 * bz0));
        const float w1 = -0.5f * fmaf(bx1, bx1, fmaf(by1, by1, bz1 * bz1));
        sB[2 * q]     = make_float4(bx0, bx1, by0, by1);
        sB[2 * q + 1] = make_float4(bz0, bz1, w0, w1);
    }

    // Per-thread A points: duplicated f32x2 coords (loop-invariant packs)
    unsigned long long ax2[PTS_PER_THREAD], ay2[PTS_PER_THREAD], az2[PTS_PER_THREAD];
    float m0[PTS_PER_THREAD], m1[PTS_PER_THREAD];
    #pragma unroll
    for (int p = 0; p < PTS_PER_THREAD; p++) {
        const int i = blockIdx.x * PTS_PER_BLOCK + p * THREADS + tid;
        const float ax = A[i * 3 + 0];
        const float ay = A[i * 3 + 1];
        const float az = A[i * 3 + 2];
        ax2[p] = pack2(ax, ax);
        ay2[p] = pack2(ay, ay);
        az2[p] = pack2(az, az);
        m0[p] = -3.0e38f;
        m1[p] = -3.0e38f;
    }
    __syncthreads();

    const ulonglong2* __restrict__ sB64 = (const ulonglong2*)sB;

    #pragma unroll 2
    for (int q = 0; q < BRANGE / 2; q++) {
        const ulonglong2 v0 = sB64[2 * q];       // .x = (bx0,bx1), .y = (by0,by1)
        const ulonglong2 v1 = sB64[2 * q + 1];   // .x = (bz0,bz1), .y = (w0, w1)
        #pragma unroll
        for (int p = 0; p < PTS_PER_THREAD; p++) {
            unsigned long long t = fma2(v0.x, ax2[p], v1.y);   // bx*ax + w
            t = fma2(v0.y, ay2[p], t);                         // + by*ay
            t = fma2(v1.x, az2[p], t);                         // + bz*az
            U64F2 u; u.u = t;
            m0[p] = fmaxf(m0[p], u.f.x);
            m1[p] = fmaxf(m1[p], u.f.y);
        }
    }

    // Write per-point partial max for this B-split
    #pragma unroll
    for (int p = 0; p < PTS_PER_THREAD; p++) {
        const int i = blockIdx.x * PTS_PER_BLOCK + p * THREADS + tid;
        const size_t idx = ((size_t)(dir * BATCH + b) * NPTS + i) * NSPLIT + split;
        g_partial[idx] = fmaxf(m0[p], m1[p]);
    }
}

// One thread per (dir, batch, point): combine splits, sqrt, reduce, atomic.
__global__ __launch_bounds__(256)
void chamfer_combine_kernel(const float* __restrict__ pred,
                            const float* __restrict__ label,
                            float* __restrict__ out) {
    const int idx = blockIdx.x * 256 + threadIdx.x;   // 0 .. 65535
    const int dir = idx >> 15;
    const int rem = idx & 32767;                       // b*NPTS + i
    const float* __restrict__ A = ((dir == 0) ? pred : label) + (size_t)rem * 3;
    const float ax = A[0], ay = A[1], az = A[2];
    const float x2 = fmaf(ax, ax, fmaf(ay, ay, az * az));

    const float* pp = &g_partial[(size_t)idx * NSPLIT];
    const float m = fmaxf(fmaxf(pp[0], pp[1]), fmaxf(pp[2], pp[3]));
    const float d = sqrtf(fmaxf(fmaf(-2.0f, m, x2), 0.0f));
    float s = d * (1.0f / (float)(BATCH * NPTS));

    #pragma unroll
    for (int off = 16; off > 0; off >>= 1)
        s += __shfl_down_sync(0xFFFFFFFFu, s, off);

    __shared__ float warp_sums[8];
    const int tid = threadIdx.x;
    if ((tid & 31) == 0) warp_sums[tid >> 5] = s;
    __syncthreads();
    if (tid == 0) {
        float bs = 0.0f;
        #pragma unroll
        for (int w = 0; w < 8; w++) bs += warp_sums[w];
        atomicAdd(out, bs);
    }
}

extern "C" void kernel_launch(void* const* d_in, const int* in_sizes, int n_in,
                              void* d_out, int out_size) {
    const float* pred  = (const float*)d_in[0];
    const float* label = (const float*)d_in[1];
    float* out = (float*)d_out;

    chamfer_init_kernel<<<1, 1>>>(out);
    dim3 grid(NCHUNK, BATCH, 2 * NSPLIT);   // 8 x 4 x 8 = 256 blocks
    chamfer_main_kernel<<<grid, THREADS>>>(pred, label);
    chamfer_combine_kernel<<<(2 * BATCH * NPTS) / 256, 256>>>(pred, label, out);
}

// round 3
// speedup vs baseline: 1.6970x; 1.0899x over previous
#include <cuda_runtime.h>
#include <math.h>

#define BATCH 4
#define NPTS  8192
#define NSPLIT 16
#define BRANGE (NPTS / NSPLIT)            // 512 B-points per block
#define NPAIR  (BRANGE / 2)               // 256 packed B-pairs
#define PTS_PER_THREAD 8
#define THREADS 128
#define PTS_PER_BLOCK (PTS_PER_THREAD * THREADS)  // 1024
#define NCHUNK (NPTS / PTS_PER_BLOCK)             // 8
#define COMBINE_BLOCKS 256

// Partial max(x.y - y^2/2) per (dir, batch, point, split). 4 MB static scratch.
__device__ float g_partial[2 * BATCH * NPTS * NSPLIT];
__device__ float g_bsum[COMBINE_BLOCKS];
__device__ unsigned int g_counter = 0;

union U64F2 { unsigned long long u; float2 f; };

__device__ __forceinline__ unsigned long long fma2(unsigned long long a,
                                                   unsigned long long b,
                                                   unsigned long long c) {
    unsigned long long d;
    asm("fma.rn.f32x2 %0, %1, %2, %3;" : "=l"(d) : "l"(a), "l"(b), "l"(c));
    return d;
}

__device__ __forceinline__ unsigned long long pack2(float lo, float hi) {
    U64F2 u; u.f = make_float2(lo, hi); return u.u;
}

// blockIdx.z = dir*NSPLIT + split ; blockIdx.y = batch ; blockIdx.x = A-chunk
__global__ __launch_bounds__(THREADS, 5)
void chamfer_main_kernel(const float* __restrict__ pred,
                         const float* __restrict__ label) {
    const int z     = blockIdx.z;
    const int dir   = z >> 4;
    const int split = z & 15;
    const int b     = blockIdx.y;
    const float* __restrict__ A  = ((dir == 0) ? pred  : label) + (size_t)b * NPTS * 3;
    const float* __restrict__ Bt = ((dir == 0) ? label : pred)  + (size_t)b * NPTS * 3
                                   + (size_t)split * BRANGE * 3;

    // Pair layout: slot 2q = (bx0,bx1,by0,by1), slot 2q+1 = (bz0,bz1,w0,w1), w = -0.5*||y||^2
    __shared__ float4 sB[BRANGE];   // 8 KB

    const int tid = threadIdx.x;

    // Cooperative tile load + precompute w (2 pairs per thread)
    #pragma unroll
    for (int q = tid; q < NPAIR; q += THREADS) {
        const float* p = Bt + (size_t)(2 * q) * 3;
        const float bx0 = p[0], by0 = p[1], bz0 = p[2];
        const float bx1 = p[3], by1 = p[4], bz1 = p[5];
        const float w0 = -0.5f * fmaf(bx0, bx0, fmaf(by0, by0, bz0 * bz0));
        const float w1 = -0.5f * fmaf(bx1, bx1, fmaf(by1, by1, bz1 * bz1));
        sB[2 * q]     = make_float4(bx0, bx1, by0, by1);
        sB[2 * q + 1] = make_float4(bz0, bz1, w0, w1);
    }

    // Per-thread A points: duplicated f32x2 coords (loop-invariant packs)
    unsigned long long ax2[PTS_PER_THREAD], ay2[PTS_PER_THREAD], az2[PTS_PER_THREAD];
    float m0[PTS_PER_THREAD], m1[PTS_PER_THREAD];
    #pragma unroll
    for (int p = 0; p < PTS_PER_THREAD; p++) {
        const int i = blockIdx.x * PTS_PER_BLOCK + p * THREADS + tid;
        const float ax = A[i * 3 + 0];
        const float ay = A[i * 3 + 1];
        const float az = A[i * 3 + 2];
        ax2[p] = pack2(ax, ax);
        ay2[p] = pack2(ay, ay);
        az2[p] = pack2(az, az);
        m0[p] = -3.0e38f;
        m1[p] = -3.0e38f;
    }
    __syncthreads();

    const ulonglong2* __restrict__ sB64 = (const ulonglong2*)sB;

    #pragma unroll 4
    for (int q = 0; q < NPAIR; q++) {
        const ulonglong2 v0 = sB64[2 * q];       // .x = (bx0,bx1), .y = (by0,by1)
        const ulonglong2 v1 = sB64[2 * q + 1];   // .x = (bz0,bz1), .y = (w0, w1)
        #pragma unroll
        for (int p = 0; p < PTS_PER_THREAD; p++) {
            unsigned long long t = fma2(v0.x, ax2[p], v1.y);   // bx*ax + w
            t = fma2(v0.y, ay2[p], t);                         // + by*ay
            t = fma2(v1.x, az2[p], t);                         // + bz*az
            U64F2 u; u.u = t;
            m0[p] = fmaxf(m0[p], u.f.x);
            m1[p] = fmaxf(m1[p], u.f.y);
        }
    }

    // Write per-point partial max for this B-split
    #pragma unroll
    for (int p = 0; p < PTS_PER_THREAD; p++) {
        const int i = blockIdx.x * PTS_PER_BLOCK + p * THREADS + tid;
        const size_t idx = ((size_t)(dir * BATCH + b) * NPTS + i) * NSPLIT + split;
        g_partial[idx] = fmaxf(m0[p], m1[p]);
    }
}

// One thread per (dir, batch, point): combine splits, sqrt, reduce.
// Last-block-done pattern finalizes the scalar (no separate init kernel).
__global__ __launch_bounds__(256)
void chamfer_combine_kernel(const float* __restrict__ pred,
                            const float* __restrict__ label,
                            float* __restrict__ out) {
    const int idx = blockIdx.x * 256 + threadIdx.x;   // 0 .. 65535
    const int dir = idx >> 15;
    const int rem = idx & 32767;                       // b*NPTS + i
    const float* __restrict__ A = ((dir == 0) ? pred : label) + (size_t)rem * 3;
    const float ax = A[0], ay = A[1], az = A[2];
    const float x2 = fmaf(ax, ax, fmaf(ay, ay, az * az));

    const float4* pp = (const float4*)&g_partial[(size_t)idx * NSPLIT];
    float m = -3.0e38f;
    #pragma unroll
    for (int k = 0; k < NSPLIT / 4; k++) {
        const float4 v = pp[k];
        m = fmaxf(m, fmaxf(fmaxf(v.x, v.y), fmaxf(v.z, v.w)));
    }
    const float d = sqrtf(fmaxf(fmaf(-2.0f, m, x2), 0.0f));
    float s = d;

    #pragma unroll
    for (int off = 16; off > 0; off >>= 1)
        s += __shfl_down_sync(0xFFFFFFFFu, s, off);

    __shared__ float warp_sums[8];
    __shared__ bool is_last;
    const int tid = threadIdx.x;
    if ((tid & 31) == 0) warp_sums[tid >> 5] = s;
    __syncthreads();
    if (tid == 0) {
        float bs = 0.0f;
        #pragma unroll
        for (int w = 0; w < 8; w++) bs += warp_sums[w];
        g_bsum[blockIdx.x] = bs;
        __threadfence();
        const unsigned int done = atomicAdd(&g_counter, 1u) + 1u;
        is_last = (done == COMBINE_BLOCKS);
    }
    __syncthreads();

    if (is_last) {
        // Final reduction over block sums; thread count == COMBINE_BLOCKS.
        float v = g_bsum[tid];
        #pragma unroll
        for (int off = 16; off > 0; off >>= 1)
            v += __shfl_down_sync(0xFFFFFFFFu, v, off);
        if ((tid & 31) == 0) warp_sums[tid >> 5] = v;
        __syncthreads();
        if (tid == 0) {
            float tot = 0.0f;
            #pragma unroll
            for (int w = 0; w < 8; w++) tot += warp_sums[w];
            out[0] = tot * (1.0f / (float)(BATCH * NPTS));
            g_counter = 0;   // reset for next graph replay (deterministic)
        }
    }
}

extern "C" void kernel_launch(void* const* d_in, const int* in_sizes, int n_in,
                              void* d_out, int out_size) {
    const float* pred  = (const float*)d_in[0];
    const float* label = (const float*)d_in[1];
    float* out = (float*)d_out;

    dim3 grid(NCHUNK, BATCH, 2 * NSPLIT);   // 8 x 4 x 32 = 1024 blocks
    chamfer_main_kernel<<<grid, THREADS>>>(pred, label);
    chamfer_combine_kernel<<<COMBINE_BLOCKS, 256>>>(pred, label, out);
}